// round 2
// baseline (speedup 1.0000x reference)
#include <cuda_runtime.h>

// Problem constants (fixed by the dataset)
#define NMAX 50000
#define EMAX 640000

// Scratch (device globals — no allocation allowed)
__device__ float g_h [NMAX * 128];   // per-layer transformed features
__device__ float g_x2[NMAX * 128];   // layer-1 output / layer-2 input
__device__ float g_as[NMAX * 4];
__device__ float g_ad[NMAX * 4];
__device__ int   g_deg[NMAX];
__device__ int   g_off[NMAX + 1];
__device__ int   g_cur[NMAX];
__device__ int   g_csr[EMAX];

// ---------------------------------------------------------------------------
// CSR build
// ---------------------------------------------------------------------------
__global__ void zero_kernel(int n) {
    int i = blockIdx.x * blockDim.x + threadIdx.x;
    if (i < n) { g_deg[i] = 0; g_cur[i] = 0; }
}

// edge_index is int32 (JAX default x64-disabled): layout [2, E] row-major.
__global__ void hist_kernel(const int* __restrict__ ei, int E) {
    int e = blockIdx.x * blockDim.x + threadIdx.x;
    if (e < E) {
        int d = ei[E + e];
        atomicAdd(&g_deg[d], 1);
    }
}

// Single-block exclusive scan of g_deg -> g_off
__global__ void scan_kernel(int n) {
    __shared__ int sums[1024];
    int tid = threadIdx.x;
    int per = (n + 1023) >> 10;
    int start = tid * per;
    int s = 0;
    for (int i = 0; i < per; i++) {
        int idx = start + i;
        if (idx < n) s += g_deg[idx];
    }
    sums[tid] = s;
    __syncthreads();
    int own = s;
    for (int o = 1; o < 1024; o <<= 1) {
        int v = (tid >= o) ? sums[tid - o] : 0;
        __syncthreads();
        sums[tid] += v;
        __syncthreads();
    }
    int run = sums[tid] - own;   // exclusive prefix of this thread's chunk
    for (int i = 0; i < per; i++) {
        int idx = start + i;
        if (idx < n) { g_off[idx] = run; run += g_deg[idx]; }
    }
    if (tid == 1023) g_off[n] = run;
}

__global__ void fill_kernel(const int* __restrict__ ei, int E) {
    int e = blockIdx.x * blockDim.x + threadIdx.x;
    if (e < E) {
        int s = ei[e];
        int d = ei[E + e];
        int p = g_off[d] + atomicAdd(&g_cur[d], 1);
        g_csr[p] = s;
    }
}

// ---------------------------------------------------------------------------
// Fused GEMM (h = X @ W) + per-head attention coefficients
// block = (32, 8): 32 rows x 128 cols per block, 4x4 register tile / thread
// ---------------------------------------------------------------------------
__global__ void gemm_alpha_kernel(const float* __restrict__ Xparam, int use_gx2,
                                  const float* __restrict__ W,
                                  const float* __restrict__ a_src,
                                  const float* __restrict__ a_dst,
                                  int N) {
    __shared__ __align__(16) float xs[32][128];
    const float* X = use_gx2 ? (const float*)g_x2 : Xparam;

    int tx = threadIdx.x;               // 0..31  -> cols 4*tx..4*tx+3
    int ty = threadIdx.y;               // 0..7   -> rows 4*ty..4*ty+3 (warp = fixed ty)
    int tid = ty * 32 + tx;
    int row0 = blockIdx.x * 32;

    // stage 32 x-rows (float4 loads)
    for (int t = tid; t < 1024; t += 256) {
        int r = t >> 5, c = t & 31;
        float4 v = make_float4(0.f, 0.f, 0.f, 0.f);
        int row = row0 + r;
        if (row < N) v = __ldg((const float4*)X + (size_t)row * 32 + c);
        *(float4*)&xs[r][c * 4] = v;
    }
    __syncthreads();

    float acc[4][4];
#pragma unroll
    for (int i = 0; i < 4; i++)
#pragma unroll
        for (int j = 0; j < 4; j++) acc[i][j] = 0.f;

#pragma unroll 4
    for (int k = 0; k < 128; k++) {
        float4 w = __ldg((const float4*)W + k * 32 + tx);  // W[k][4tx..4tx+3]
        float x0 = xs[ty * 4 + 0][k];
        float x1 = xs[ty * 4 + 1][k];
        float x2 = xs[ty * 4 + 2][k];
        float x3 = xs[ty * 4 + 3][k];
        acc[0][0] += x0 * w.x; acc[0][1] += x0 * w.y; acc[0][2] += x0 * w.z; acc[0][3] += x0 * w.w;
        acc[1][0] += x1 * w.x; acc[1][1] += x1 * w.y; acc[1][2] += x1 * w.z; acc[1][3] += x1 * w.w;
        acc[2][0] += x2 * w.x; acc[2][1] += x2 * w.y; acc[2][2] += x2 * w.z; acc[2][3] += x2 * w.w;
        acc[3][0] += x3 * w.x; acc[3][1] += x3 * w.y; acc[3][2] += x3 * w.z; acc[3][3] += x3 * w.w;
    }

    float4 asv = __ldg((const float4*)a_src + tx);  // a_src flat[j], j = head*32+c
    float4 adv = __ldg((const float4*)a_dst + tx);

#pragma unroll
    for (int i = 0; i < 4; i++) {
        int row = row0 + ty * 4 + i;        // same row for all lanes of this warp
        if (row < N) {
            float4 hv = make_float4(acc[i][0], acc[i][1], acc[i][2], acc[i][3]);
            *((float4*)g_h + (size_t)row * 32 + tx) = hv;
            float pa = hv.x * asv.x + hv.y * asv.y + hv.z * asv.z + hv.w * asv.w;
            float pd = hv.x * adv.x + hv.y * adv.y + hv.z * adv.z + hv.w * adv.w;
            // reduce within 8-lane head groups (lanes 0-7 = head 0, ...)
#pragma unroll
            for (int o = 4; o >= 1; o >>= 1) {
                pa += __shfl_xor_sync(0xffffffffu, pa, o);
                pd += __shfl_xor_sync(0xffffffffu, pd, o);
            }
            if ((tx & 7) == 0) {
                g_as[row * 4 + (tx >> 3)] = pa;
                g_ad[row * 4 + (tx >> 3)] = pd;
            }
        }
    }
}

// ---------------------------------------------------------------------------
// Aggregation: one warp per dst node, online (flash-style) segment softmax.
// lane L owns columns [4L, 4L+4); head = L/8. Self loop folded into init.
// ---------------------------------------------------------------------------
__global__ void agg_kernel(float* __restrict__ outparam, int out_to_gx2,
                           const float* __restrict__ bias, int relu, int N) {
    int lane = threadIdx.x & 31;
    int n = (blockIdx.x * blockDim.x + threadIdx.x) >> 5;
    if (n >= N) return;

    float* out = out_to_gx2 ? (float*)g_x2 : outparam;
    const float4* H4 = (const float4*)g_h;
    int head = lane >> 3;

    float adn = g_ad[n * 4 + head];
    float e0 = g_as[n * 4 + head] + adn;
    e0 = e0 > 0.f ? e0 : 0.2f * e0;

    float m = e0;
    float d = 1.f;
    float4 acc = H4[(size_t)n * 32 + lane];   // self loop, weight exp(0)=1

    int p0 = g_off[n], p1 = g_off[n + 1];
    for (int p = p0; p < p1; p++) {
        int s = g_csr[p];
        float e = g_as[s * 4 + head] + adn;
        e = e > 0.f ? e : 0.2f * e;
        float w;
        if (e > m) {
            float f = __expf(m - e);
            acc.x *= f; acc.y *= f; acc.z *= f; acc.w *= f;
            d *= f;
            m = e;
            w = 1.f;
        } else {
            w = __expf(e - m);
        }
        float4 hv = H4[(size_t)s * 32 + lane];
        d += w;
        acc.x += w * hv.x; acc.y += w * hv.y; acc.z += w * hv.z; acc.w += w * hv.w;
    }

    float inv = 1.f / (d + 1e-16f);
    float4 bb = __ldg((const float4*)bias + lane);
    float4 o;
    o.x = acc.x * inv + bb.x;
    o.y = acc.y * inv + bb.y;
    o.z = acc.z * inv + bb.z;
    o.w = acc.w * inv + bb.w;
    if (relu) {
        o.x = fmaxf(o.x, 0.f); o.y = fmaxf(o.y, 0.f);
        o.z = fmaxf(o.z, 0.f); o.w = fmaxf(o.w, 0.f);
    }
    ((float4*)out)[(size_t)n * 32 + lane] = o;
}

// ---------------------------------------------------------------------------
// Launch
// ---------------------------------------------------------------------------
extern "C" void kernel_launch(void* const* d_in, const int* in_sizes, int n_in,
                              void* d_out, int out_size) {
    const float* x   = (const float*)d_in[0];
    const int*   ei  = (const int*)d_in[1];   // int32 (JAX default)
    const float* W1  = (const float*)d_in[2];
    const float* as1 = (const float*)d_in[3];
    const float* ad1 = (const float*)d_in[4];
    const float* b1  = (const float*)d_in[5];
    const float* W2  = (const float*)d_in[6];
    const float* as2 = (const float*)d_in[7];
    const float* ad2 = (const float*)d_in[8];
    const float* b2  = (const float*)d_in[9];

    int N = in_sizes[0] / 128;
    int E = in_sizes[1] / 2;

    // CSR build (reused by both layers)
    zero_kernel<<<(N + 255) / 256, 256>>>(N);
    hist_kernel<<<(E + 255) / 256, 256>>>(ei, E);
    scan_kernel<<<1, 1024>>>(N);
    fill_kernel<<<(E + 255) / 256, 256>>>(ei, E);

    dim3 gblk(32, 8);
    int ggrid = (N + 31) / 32;
    int ablk = 256;                       // 8 warps = 8 nodes / block
    int agrid = (N + 7) / 8;

    // Layer 1: h = x@W1 ; agg -> relu(.)+b1 -> g_x2
    gemm_alpha_kernel<<<ggrid, gblk>>>(x, 0, W1, as1, ad1, N);
    agg_kernel<<<agrid, ablk>>>(nullptr, 1, b1, 1, N);

    // Layer 2: h = g_x2@W2 ; agg -> +b2 -> d_out
    gemm_alpha_kernel<<<ggrid, gblk>>>(nullptr, 1, W2, as2, ad2, N);
    agg_kernel<<<agrid, ablk>>>((float*)d_out, 0, b2, 0, N);
}

// round 3
// speedup vs baseline: 1.1563x; 1.1563x over previous
#include <cuda_runtime.h>

#define NMAX 50000
#define EMAX 640000

// Scratch (device globals — no allocation allowed)
__device__ float g_h [NMAX * 128];   // per-layer transformed features
__device__ float g_x2[NMAX * 128];   // layer-1 output / layer-2 input
__device__ float g_as[NMAX * 4];
__device__ float g_ad[NMAX * 4];
__device__ int   g_deg[NMAX];
__device__ int   g_off[NMAX + 1];
__device__ int   g_cur[NMAX];
__device__ int   g_csr[EMAX];

// ---------------------------------------------------------------------------
// packed fp32x2 FMA (SASS FFMA2) — only reachable via PTX
// ---------------------------------------------------------------------------
__device__ __forceinline__ void ffma2(float2& d, float2 a, float2 b) {
    asm("fma.rn.f32x2 %0, %1, %2, %0;"
        : "+l"(reinterpret_cast<unsigned long long&>(d))
        : "l"(reinterpret_cast<unsigned long long&>(a)),
          "l"(reinterpret_cast<unsigned long long&>(b)));
}

// ---------------------------------------------------------------------------
// CSR build
// ---------------------------------------------------------------------------
__global__ void zero_kernel(int n) {
    int i = blockIdx.x * blockDim.x + threadIdx.x;
    if (i < n) { g_deg[i] = 0; g_cur[i] = 0; }
}

__global__ void hist_kernel(const int* __restrict__ ei, int E) {
    int e = blockIdx.x * blockDim.x + threadIdx.x;
    if (e < E) {
        int d = __ldg(&ei[E + e]);
        atomicAdd(&g_deg[d], 1);
    }
}

__global__ void scan_kernel(int n) {
    __shared__ int sums[1024];
    int tid = threadIdx.x;
    int per = (n + 1023) >> 10;
    int start = tid * per;
    int s = 0;
    for (int i = 0; i < per; i++) {
        int idx = start + i;
        if (idx < n) s += g_deg[idx];
    }
    sums[tid] = s;
    __syncthreads();
    int own = s;
    for (int o = 1; o < 1024; o <<= 1) {
        int v = (tid >= o) ? sums[tid - o] : 0;
        __syncthreads();
        sums[tid] += v;
        __syncthreads();
    }
    int run = sums[tid] - own;
    for (int i = 0; i < per; i++) {
        int idx = start + i;
        if (idx < n) { g_off[idx] = run; run += g_deg[idx]; }
    }
    if (tid == 1023) g_off[n] = run;
}

__global__ void fill_kernel(const int* __restrict__ ei, int E) {
    int e = blockIdx.x * blockDim.x + threadIdx.x;
    if (e < E) {
        int s = __ldg(&ei[e]);
        int d = __ldg(&ei[E + e]);
        int p = g_off[d] + atomicAdd(&g_cur[d], 1);
        g_csr[p] = s;
    }
}

// ---------------------------------------------------------------------------
// FFMA2 GEMM: g_h[64-row tile][128] = X @ W
// 128 threads = 4 warps; warp = 16 rows x 128 cols; thread = 8 rows x 8 cols
// rows paired in fp32x2 accumulators; x staged k-transposed, W staged duplicated
// ---------------------------------------------------------------------------
#define GR 64
__global__ void __launch_bounds__(128) gemm_ffma2_kernel(
        const float* __restrict__ Xparam, int use_gx2,
        const float* __restrict__ W, int N) {
    __shared__ __align__(16) float xt[32][66];    // [kk][row], pad 2 -> 2-way STS max
    __shared__ __align__(16) float ws[32][256];   // [kk][2*c] = (W,W) duplicated

    const float* X = use_gx2 ? (const float*)g_x2 : Xparam;
    int tid  = threadIdx.x;
    int lane = tid & 31;
    int w    = tid >> 5;            // warp 0..3
    int rgrp = lane >> 4;           // 0..1
    int cgrp = lane & 15;           // 0..15
    int row0 = blockIdx.x * GR;
    int base_r = w * 16 + rgrp * 8; // thread rows: base_r .. base_r+7

    float2 acc[4][8];               // [row-pair][j*2 + col01]
#pragma unroll
    for (int i = 0; i < 4; i++)
#pragma unroll
        for (int j = 0; j < 8; j++) acc[i][j] = make_float2(0.f, 0.f);

    for (int ck = 0; ck < 4; ck++) {
        int k0 = ck * 32;
        // stage x transposed: xt[kk][r] = X[row0+r][k0+kk]
#pragma unroll
        for (int i = 0; i < 16; i++) {
            int r = w * 16 + i;
            int row = row0 + r;
            float v = (row < N) ? __ldg(&X[(size_t)row * 128 + k0 + lane]) : 0.f;
            xt[lane][r] = v;
        }
        // stage W duplicated: ws[kk][2c..2c+1] = (W[k0+kk][c], same)
#pragma unroll
        for (int i = 0; i < 32; i++) {
            int idx = i * 128 + tid;
            int kk = idx >> 7, c = idx & 127;
            float v = __ldg(&W[(k0 + kk) * 128 + c]);
            *(float2*)&ws[kk][2 * c] = make_float2(v, v);
        }
        __syncthreads();

#pragma unroll 4
        for (int kk = 0; kk < 32; kk++) {
            float2 xp[4];
#pragma unroll
            for (int i = 0; i < 4; i++)
                xp[i] = *(const float2*)&xt[kk][base_r + 2 * i];
#pragma unroll
            for (int j = 0; j < 4; j++) {
                // cols (cgrp*2 + 32j, +1) duplicated pairs
                float4 wv = *(const float4*)&ws[kk][4 * cgrp + 64 * j];
                float2 w0 = make_float2(wv.x, wv.y);
                float2 w1 = make_float2(wv.z, wv.w);
#pragma unroll
                for (int i = 0; i < 4; i++) {
                    ffma2(acc[i][2 * j],     xp[i], w0);
                    ffma2(acc[i][2 * j + 1], xp[i], w1);
                }
            }
        }
        __syncthreads();
    }

    // epilogue: scatter packed row-pairs to g_h
#pragma unroll
    for (int i = 0; i < 4; i++) {
        int re = row0 + base_r + 2 * i;
        if (re < N) {
#pragma unroll
            for (int j = 0; j < 4; j++) {
                float2 v = make_float2(acc[i][2 * j].x, acc[i][2 * j + 1].x);
                *(float2*)&g_h[(size_t)re * 128 + cgrp * 2 + 32 * j] = v;
            }
        }
        int ro = re + 1;
        if (ro < N) {
#pragma unroll
            for (int j = 0; j < 4; j++) {
                float2 v = make_float2(acc[i][2 * j].y, acc[i][2 * j + 1].y);
                *(float2*)&g_h[(size_t)ro * 128 + cgrp * 2 + 32 * j] = v;
            }
        }
    }
}

// ---------------------------------------------------------------------------
// attention coefficients: warp per row, per-head 8-lane reduction
// ---------------------------------------------------------------------------
__global__ void alpha_kernel(const float* __restrict__ a_src,
                             const float* __restrict__ a_dst, int N) {
    int lane = threadIdx.x & 31;
    int row = (blockIdx.x * blockDim.x + threadIdx.x) >> 5;
    if (row >= N) return;
    float4 hv  = *((const float4*)g_h + (size_t)row * 32 + lane);
    float4 asv = __ldg((const float4*)a_src + lane);
    float4 adv = __ldg((const float4*)a_dst + lane);
    float pa = hv.x * asv.x + hv.y * asv.y + hv.z * asv.z + hv.w * asv.w;
    float pd = hv.x * adv.x + hv.y * adv.y + hv.z * adv.z + hv.w * adv.w;
#pragma unroll
    for (int o = 4; o >= 1; o >>= 1) {
        pa += __shfl_xor_sync(0xffffffffu, pa, o);
        pd += __shfl_xor_sync(0xffffffffu, pd, o);
    }
    if ((lane & 7) == 0) {
        g_as[row * 4 + (lane >> 3)] = pa;
        g_ad[row * 4 + (lane >> 3)] = pd;
    }
}

// ---------------------------------------------------------------------------
// Aggregation: warp per dst node, online segment softmax, self-loop in init
// ---------------------------------------------------------------------------
__global__ void agg_kernel(float* __restrict__ outparam, int out_to_gx2,
                           const float* __restrict__ bias, int relu, int N) {
    int lane = threadIdx.x & 31;
    int n = (blockIdx.x * blockDim.x + threadIdx.x) >> 5;
    if (n >= N) return;

    float* out = out_to_gx2 ? (float*)g_x2 : outparam;
    const float4* H4 = (const float4*)g_h;
    int head = lane >> 3;

    float adn = g_ad[n * 4 + head];
    float e0 = g_as[n * 4 + head] + adn;
    e0 = e0 > 0.f ? e0 : 0.2f * e0;

    float m = e0;
    float d = 1.f;
    float4 acc = H4[(size_t)n * 32 + lane];   // self loop, weight exp(0)=1

    int p0 = g_off[n], p1 = g_off[n + 1];
    for (int p = p0; p < p1; p++) {
        int s = __ldg(&g_csr[p]);
        float e = g_as[s * 4 + head] + adn;
        e = e > 0.f ? e : 0.2f * e;
        float wgt;
        if (e > m) {
            float f = __expf(m - e);
            acc.x *= f; acc.y *= f; acc.z *= f; acc.w *= f;
            d *= f;
            m = e;
            wgt = 1.f;
        } else {
            wgt = __expf(e - m);
        }
        float4 hv = H4[(size_t)s * 32 + lane];
        d += wgt;
        acc.x += wgt * hv.x; acc.y += wgt * hv.y;
        acc.z += wgt * hv.z; acc.w += wgt * hv.w;
    }

    float inv = 1.f / (d + 1e-16f);
    float4 bb = __ldg((const float4*)bias + lane);
    float4 o;
    o.x = acc.x * inv + bb.x;
    o.y = acc.y * inv + bb.y;
    o.z = acc.z * inv + bb.z;
    o.w = acc.w * inv + bb.w;
    if (relu) {
        o.x = fmaxf(o.x, 0.f); o.y = fmaxf(o.y, 0.f);
        o.z = fmaxf(o.z, 0.f); o.w = fmaxf(o.w, 0.f);
    }
    ((float4*)out)[(size_t)n * 32 + lane] = o;
}

// ---------------------------------------------------------------------------
// Launch
// ---------------------------------------------------------------------------
extern "C" void kernel_launch(void* const* d_in, const int* in_sizes, int n_in,
                              void* d_out, int out_size) {
    const float* x   = (const float*)d_in[0];
    const int*   ei  = (const int*)d_in[1];   // int32 (JAX default)
    const float* W1  = (const float*)d_in[2];
    const float* as1 = (const float*)d_in[3];
    const float* ad1 = (const float*)d_in[4];
    const float* b1  = (const float*)d_in[5];
    const float* W2  = (const float*)d_in[6];
    const float* as2 = (const float*)d_in[7];
    const float* ad2 = (const float*)d_in[8];
    const float* b2  = (const float*)d_in[9];

    int N = in_sizes[0] / 128;
    int E = in_sizes[1] / 2;

    // CSR build (reused by both layers)
    zero_kernel<<<(N + 255) / 256, 256>>>(N);
    hist_kernel<<<(E + 255) / 256, 256>>>(ei, E);
    scan_kernel<<<1, 1024>>>(N);
    fill_kernel<<<(E + 255) / 256, 256>>>(ei, E);

    int ggrid = (N + GR - 1) / GR;
    int lgrid = (N + 7) / 8;      // alpha: 8 rows / 256-thr block
    int agrid = (N + 7) / 8;      // agg:   8 nodes / 256-thr block

    // Layer 1
    gemm_ffma2_kernel<<<ggrid, 128>>>(x, 0, W1, N);
    alpha_kernel<<<lgrid, 256>>>(as1, ad1, N);
    agg_kernel<<<agrid, 256>>>(nullptr, 1, b1, 1, N);

    // Layer 2
    gemm_ffma2_kernel<<<ggrid, 128>>>(nullptr, 1, W2, N);
    alpha_kernel<<<lgrid, 256>>>(as2, ad2, N);
    agg_kernel<<<agrid, 256>>>((float*)d_out, 0, b2, 0, N);
}

// round 4
// speedup vs baseline: 1.2062x; 1.0431x over previous
#include <cuda_runtime.h>

#define NMAX 50000
#define EMAX 640000

__device__ float g_h [NMAX * 128];
__device__ float g_x2[NMAX * 128];
__device__ float g_as[NMAX * 4];
__device__ float g_ad[NMAX * 4];
__device__ int   g_deg[NMAX];
__device__ int   g_off[NMAX + 1];
__device__ int   g_cur[NMAX];
__device__ int   g_csr[EMAX];

// packed fp32x2 FMA (SASS FFMA2) — only reachable via PTX
__device__ __forceinline__ void ffma2(float2& d, float2 a, float2 b) {
    asm("fma.rn.f32x2 %0, %1, %2, %0;"
        : "+l"(reinterpret_cast<unsigned long long&>(d))
        : "l"(reinterpret_cast<unsigned long long&>(a)),
          "l"(reinterpret_cast<unsigned long long&>(b)));
}

// ---------------------------------------------------------------------------
// CSR build
// ---------------------------------------------------------------------------
__global__ void zero_kernel(int n) {
    int i = blockIdx.x * blockDim.x + threadIdx.x;
    if (i < n) { g_deg[i] = 0; g_cur[i] = 0; }
}

__global__ void hist_kernel(const int* __restrict__ ei, int E) {
    int base = (blockIdx.x * blockDim.x + threadIdx.x) * 4;
    if (base + 3 < E) {
        int4 d = *(const int4*)&ei[E + base];
        atomicAdd(&g_deg[d.x], 1);
        atomicAdd(&g_deg[d.y], 1);
        atomicAdd(&g_deg[d.z], 1);
        atomicAdd(&g_deg[d.w], 1);
    } else {
        for (int e = base; e < E; e++) atomicAdd(&g_deg[__ldg(&ei[E + e])], 1);
    }
}

__global__ void scan_kernel(int n) {
    __shared__ int sums[1024];
    int tid = threadIdx.x;
    int per = (n + 1023) >> 10;
    int start = tid * per;
    int s = 0;
    for (int i = 0; i < per; i++) {
        int idx = start + i;
        if (idx < n) s += g_deg[idx];
    }
    sums[tid] = s;
    __syncthreads();
    int own = s;
    for (int o = 1; o < 1024; o <<= 1) {
        int v = (tid >= o) ? sums[tid - o] : 0;
        __syncthreads();
        sums[tid] += v;
        __syncthreads();
    }
    int run = sums[tid] - own;
    for (int i = 0; i < per; i++) {
        int idx = start + i;
        if (idx < n) { g_off[idx] = run; run += g_deg[idx]; }
    }
    if (tid == 1023) g_off[n] = run;
}

__global__ void fill_kernel(const int* __restrict__ ei, int E) {
    int base = (blockIdx.x * blockDim.x + threadIdx.x) * 4;
    if (base + 3 < E) {
        int4 s = *(const int4*)&ei[base];
        int4 d = *(const int4*)&ei[E + base];
        int p0 = g_off[d.x] + atomicAdd(&g_cur[d.x], 1);
        int p1 = g_off[d.y] + atomicAdd(&g_cur[d.y], 1);
        int p2 = g_off[d.z] + atomicAdd(&g_cur[d.z], 1);
        int p3 = g_off[d.w] + atomicAdd(&g_cur[d.w], 1);
        g_csr[p0] = s.x; g_csr[p1] = s.y; g_csr[p2] = s.z; g_csr[p3] = s.w;
    } else {
        for (int e = base; e < E; e++) {
            int s = __ldg(&ei[e]);
            int d = __ldg(&ei[E + e]);
            int p = g_off[d] + atomicAdd(&g_cur[d], 1);
            g_csr[p] = s;
        }
    }
}

// ---------------------------------------------------------------------------
// FFMA2 GEMM, column-paired accumulators + fused attention-coefficient dots.
// Block 128 thr, 64-row tile. Warp = 16 rows x 128 cols; thread = 8 rows x 8 cols
// (cols 4*cgrp..+3 and 64+4*cgrp..+3). x duplicated in-register via mov.b64.
// ---------------------------------------------------------------------------
#define GR 64
__global__ void __launch_bounds__(128) gemm_ffma2_kernel(
        const float* __restrict__ Xparam, int use_gx2,
        const float* __restrict__ W,
        const float* __restrict__ a_src,
        const float* __restrict__ a_dst, int N) {
    __shared__ __align__(16) float xt[32][66];    // [kk][row] transposed, 2-way STS max
    __shared__ __align__(16) float ws[32][128];   // [kk][col] natural

    const float* X = use_gx2 ? (const float*)g_x2 : Xparam;
    int tid  = threadIdx.x;
    int lane = tid & 31;
    int w    = tid >> 5;
    int rgrp = lane >> 4;            // 0..1
    int cgrp = lane & 15;            // 0..15
    int row0 = blockIdx.x * GR;
    int base_r = w * 16 + rgrp * 8;  // thread rows base_r..base_r+7
    int c0 = cgrp * 4;               // col group A: c0..c0+3 ; group B: 64+c0..64+c0+3

    float2 acc[8][4];
#pragma unroll
    for (int r = 0; r < 8; r++)
#pragma unroll
        for (int j = 0; j < 4; j++) acc[r][j] = make_float2(0.f, 0.f);

    for (int ck = 0; ck < 4; ck++) {
        int k0 = ck * 32;
        // stage x transposed: xt[kk][r] = X[row0+r][k0+kk] ; lane = kk
#pragma unroll
        for (int i = 0; i < 16; i++) {
            int r = w * 16 + i;
            int row = row0 + r;
            xt[lane][r] = (row < N) ? __ldg(&X[(size_t)row * 128 + k0 + lane]) : 0.f;
        }
        // stage W natural: 1024 float4 / 128 thr = 8 each
#pragma unroll
        for (int i = 0; i < 8; i++) {
            int idx = i * 128 + tid;           // float4 index
            int kk = idx >> 5, c4 = idx & 31;
            ((float4*)ws)[idx] = __ldg((const float4*)&W[(size_t)(k0 + kk) * 128 + c4 * 4]);
        }
        __syncthreads();

#pragma unroll 8
        for (int kk = 0; kk < 32; kk++) {
            float2 xp[4];
#pragma unroll
            for (int i = 0; i < 4; i++)
                xp[i] = *(const float2*)&xt[kk][base_r + 2 * i];
            float4 wa = *(const float4*)&ws[kk][c0];
            float4 wb = *(const float4*)&ws[kk][64 + c0];
            float2 wa0 = make_float2(wa.x, wa.y), wa1 = make_float2(wa.z, wa.w);
            float2 wb0 = make_float2(wb.x, wb.y), wb1 = make_float2(wb.z, wb.w);
#pragma unroll
            for (int i = 0; i < 4; i++) {
                float2 xd0 = make_float2(xp[i].x, xp[i].x);
                float2 xd1 = make_float2(xp[i].y, xp[i].y);
                ffma2(acc[2*i  ][0], xd0, wa0); ffma2(acc[2*i  ][1], xd0, wa1);
                ffma2(acc[2*i  ][2], xd0, wb0); ffma2(acc[2*i  ][3], xd0, wb1);
                ffma2(acc[2*i+1][0], xd1, wa0); ffma2(acc[2*i+1][1], xd1, wa1);
                ffma2(acc[2*i+1][2], xd1, wb0); ffma2(acc[2*i+1][3], xd1, wb1);
            }
        }
        __syncthreads();
    }

    // epilogue: store h + fused attention dots
    float4 asA = __ldg((const float4*)&a_src[c0]);
    float4 adA = __ldg((const float4*)&a_dst[c0]);
    float4 asB = __ldg((const float4*)&a_src[64 + c0]);
    float4 adB = __ldg((const float4*)&a_dst[64 + c0]);
    int headA = cgrp >> 3;          // 0 or 1
    int headB = 2 + headA;          // 2 or 3

#pragma unroll
    for (int r = 0; r < 8; r++) {
        int row = row0 + base_r + r;
        float4 hA = make_float4(acc[r][0].x, acc[r][0].y, acc[r][1].x, acc[r][1].y);
        float4 hB = make_float4(acc[r][2].x, acc[r][2].y, acc[r][3].x, acc[r][3].y);
        if (row < N) {
            *(float4*)&g_h[(size_t)row * 128 + c0]      = hA;
            *(float4*)&g_h[(size_t)row * 128 + 64 + c0] = hB;
        }
        float paA = hA.x*asA.x + hA.y*asA.y + hA.z*asA.z + hA.w*asA.w;
        float pdA = hA.x*adA.x + hA.y*adA.y + hA.z*adA.z + hA.w*adA.w;
        float paB = hB.x*asB.x + hB.y*asB.y + hB.z*asB.z + hB.w*asB.w;
        float pdB = hB.x*adB.x + hB.y*adB.y + hB.z*adB.z + hB.w*adB.w;
        // reduce over cgrp&7 (lane bits 0..2)
#pragma unroll
        for (int o = 4; o >= 1; o >>= 1) {
            paA += __shfl_xor_sync(0xffffffffu, paA, o);
            pdA += __shfl_xor_sync(0xffffffffu, pdA, o);
            paB += __shfl_xor_sync(0xffffffffu, paB, o);
            pdB += __shfl_xor_sync(0xffffffffu, pdB, o);
        }
        if ((cgrp & 7) == 0 && row < N) {
            g_as[row * 4 + headA] = paA;
            g_ad[row * 4 + headA] = pdA;
            g_as[row * 4 + headB] = paB;
            g_ad[row * 4 + headB] = pdB;
        }
    }
}

// ---------------------------------------------------------------------------
// Aggregation: warp per dst node, online segment softmax, prefetched edges
// ---------------------------------------------------------------------------
__global__ void agg_kernel(float* __restrict__ outparam, int out_to_gx2,
                           const float* __restrict__ bias, int relu, int N) {
    int lane = threadIdx.x & 31;
    int n = (blockIdx.x * blockDim.x + threadIdx.x) >> 5;
    if (n >= N) return;

    float* out = out_to_gx2 ? (float*)g_x2 : outparam;
    const float4* H4 = (const float4*)g_h;
    int head = lane >> 3;

    float adn = g_ad[n * 4 + head];
    float e0 = g_as[n * 4 + head] + adn;
    e0 = e0 > 0.f ? e0 : 0.2f * e0;

    float m = e0;
    float d = 1.f;
    float4 acc = H4[(size_t)n * 32 + lane];   // self loop, weight exp(0)=1

    int p0 = g_off[n], p1 = g_off[n + 1];
    int s_next = 0; float a_next = 0.f;
    if (p0 < p1) {
        s_next = __ldg(&g_csr[p0]);
        a_next = g_as[s_next * 4 + head];
    }
    for (int p = p0; p < p1; p++) {
        int s = s_next;
        float av = a_next;
        if (p + 1 < p1) {                       // prefetch next edge
            s_next = __ldg(&g_csr[p + 1]);
            a_next = g_as[s_next * 4 + head];
        }
        float e = av + adn;
        e = e > 0.f ? e : 0.2f * e;
        float wgt;
        if (e > m) {
            float f = __expf(m - e);
            acc.x *= f; acc.y *= f; acc.z *= f; acc.w *= f;
            d *= f;
            m = e;
            wgt = 1.f;
        } else {
            wgt = __expf(e - m);
        }
        float4 hv = H4[(size_t)s * 32 + lane];
        d += wgt;
        acc.x += wgt * hv.x; acc.y += wgt * hv.y;
        acc.z += wgt * hv.z; acc.w += wgt * hv.w;
    }

    float inv = 1.f / (d + 1e-16f);
    float4 bb = __ldg((const float4*)bias + lane);
    float4 o;
    o.x = acc.x * inv + bb.x;
    o.y = acc.y * inv + bb.y;
    o.z = acc.z * inv + bb.z;
    o.w = acc.w * inv + bb.w;
    if (relu) {
        o.x = fmaxf(o.x, 0.f); o.y = fmaxf(o.y, 0.f);
        o.z = fmaxf(o.z, 0.f); o.w = fmaxf(o.w, 0.f);
    }
    ((float4*)out)[(size_t)n * 32 + lane] = o;
}

// ---------------------------------------------------------------------------
// Launch
// ---------------------------------------------------------------------------
extern "C" void kernel_launch(void* const* d_in, const int* in_sizes, int n_in,
                              void* d_out, int out_size) {
    const float* x   = (const float*)d_in[0];
    const int*   ei  = (const int*)d_in[1];   // int32 (JAX default)
    const float* W1  = (const float*)d_in[2];
    const float* as1 = (const float*)d_in[3];
    const float* ad1 = (const float*)d_in[4];
    const float* b1  = (const float*)d_in[5];
    const float* W2  = (const float*)d_in[6];
    const float* as2 = (const float*)d_in[7];
    const float* ad2 = (const float*)d_in[8];
    const float* b2  = (const float*)d_in[9];

    int N = in_sizes[0] / 128;
    int E = in_sizes[1] / 2;

    // CSR build (reused by both layers)
    zero_kernel<<<(N + 255) / 256, 256>>>(N);
    hist_kernel<<<(E / 4 + 255) / 256, 256>>>(ei, E);
    scan_kernel<<<1, 1024>>>(N);
    fill_kernel<<<(E / 4 + 255) / 256, 256>>>(ei, E);

    int ggrid = (N + GR - 1) / GR;
    int agrid = (N + 7) / 8;      // 8 nodes / 256-thr block

    // Layer 1
    gemm_ffma2_kernel<<<ggrid, 128>>>(x, 0, W1, as1, ad1, N);
    agg_kernel<<<agrid, 256>>>(nullptr, 1, b1, 1, N);

    // Layer 2
    gemm_ffma2_kernel<<<ggrid, 128>>>(nullptr, 1, W2, as2, ad2, N);
    agg_kernel<<<agrid, 256>>>((float*)d_out, 0, b2, 0, N);
}

// round 5
// speedup vs baseline: 1.3196x; 1.0940x over previous
#include <cuda_runtime.h>

#define NMAX 50000
#define EMAX 640000

__device__ float g_h [NMAX * 128];
__device__ float g_x2[NMAX * 128];
__device__ float g_as[NMAX * 4];
__device__ float g_ad[NMAX * 4];
__device__ int   g_deg[NMAX];
__device__ int   g_off[NMAX + 1];
__device__ int   g_csr[EMAX];

// packed fp32x2 FMA (SASS FFMA2) — only reachable via PTX
__device__ __forceinline__ void ffma2(float2& d, float2 a, float2 b) {
    asm("fma.rn.f32x2 %0, %1, %2, %0;"
        : "+l"(reinterpret_cast<unsigned long long&>(d))
        : "l"(reinterpret_cast<unsigned long long&>(a)),
          "l"(reinterpret_cast<unsigned long long&>(b)));
}

__device__ __forceinline__ float lrelu(float e) {
    return e > 0.f ? e : 0.2f * e;
}

// ---------------------------------------------------------------------------
// CSR build
// ---------------------------------------------------------------------------
__global__ void zero_kernel(int n) {
    int i = blockIdx.x * blockDim.x + threadIdx.x;
    if (i < n) g_deg[i] = 0;
}

__global__ void hist_kernel(const int* __restrict__ ei, int E) {
    int base = (blockIdx.x * blockDim.x + threadIdx.x) * 4;
    if (base + 3 < E) {
        int4 d = *(const int4*)&ei[E + base];
        atomicAdd(&g_deg[d.x], 1);
        atomicAdd(&g_deg[d.y], 1);
        atomicAdd(&g_deg[d.z], 1);
        atomicAdd(&g_deg[d.w], 1);
    } else {
        for (int e = base; e < E; e++) atomicAdd(&g_deg[__ldg(&ei[E + e])], 1);
    }
}

__global__ void scan_kernel(int n) {
    __shared__ int sums[1024];
    int tid = threadIdx.x;
    int per = (n + 1023) >> 10;
    int start = tid * per;
    int s = 0;
    for (int i = 0; i < per; i++) {
        int idx = start + i;
        if (idx < n) s += g_deg[idx];
    }
    sums[tid] = s;
    __syncthreads();
    int own = s;
    for (int o = 1; o < 1024; o <<= 1) {
        int v = (tid >= o) ? sums[tid - o] : 0;
        __syncthreads();
        sums[tid] += v;
        __syncthreads();
    }
    int run = sums[tid] - own;
    for (int i = 0; i < per; i++) {
        int idx = start + i;
        if (idx < n) { g_off[idx] = run; run += g_deg[idx]; }
    }
    if (tid == 1023) g_off[n] = run;
}

// atomicAdd directly on g_off: afterwards g_off[n] == start of segment n+1
__global__ void fill_kernel(const int* __restrict__ ei, int E) {
    int base = (blockIdx.x * blockDim.x + threadIdx.x) * 4;
    if (base + 3 < E) {
        int4 s = *(const int4*)&ei[base];
        int4 d = *(const int4*)&ei[E + base];
        int p0 = atomicAdd(&g_off[d.x], 1);
        int p1 = atomicAdd(&g_off[d.y], 1);
        int p2 = atomicAdd(&g_off[d.z], 1);
        int p3 = atomicAdd(&g_off[d.w], 1);
        g_csr[p0] = s.x; g_csr[p1] = s.y; g_csr[p2] = s.z; g_csr[p3] = s.w;
    } else {
        for (int e = base; e < E; e++) {
            int s = __ldg(&ei[e]);
            int d = __ldg(&ei[E + e]);
            int p = atomicAdd(&g_off[d], 1);
            g_csr[p] = s;
        }
    }
}

// ---------------------------------------------------------------------------
// FFMA2 GEMM, column-paired accumulators + fused attention-coefficient dots.
// ---------------------------------------------------------------------------
#define GR 64
__global__ void __launch_bounds__(128) gemm_ffma2_kernel(
        const float* __restrict__ Xparam, int use_gx2,
        const float* __restrict__ W,
        const float* __restrict__ a_src,
        const float* __restrict__ a_dst, int N) {
    __shared__ __align__(16) float xt[32][66];
    __shared__ __align__(16) float ws[32][128];

    const float* X = use_gx2 ? (const float*)g_x2 : Xparam;
    int tid  = threadIdx.x;
    int lane = tid & 31;
    int w    = tid >> 5;
    int rgrp = lane >> 4;
    int cgrp = lane & 15;
    int row0 = blockIdx.x * GR;
    int base_r = w * 16 + rgrp * 8;
    int c0 = cgrp * 4;

    float2 acc[8][4];
#pragma unroll
    for (int r = 0; r < 8; r++)
#pragma unroll
        for (int j = 0; j < 4; j++) acc[r][j] = make_float2(0.f, 0.f);

    for (int ck = 0; ck < 4; ck++) {
        int k0 = ck * 32;
#pragma unroll
        for (int i = 0; i < 16; i++) {
            int r = w * 16 + i;
            int row = row0 + r;
            xt[lane][r] = (row < N) ? __ldg(&X[(size_t)row * 128 + k0 + lane]) : 0.f;
        }
#pragma unroll
        for (int i = 0; i < 8; i++) {
            int idx = i * 128 + tid;
            int kk = idx >> 5, c4 = idx & 31;
            ((float4*)ws)[idx] = __ldg((const float4*)&W[(size_t)(k0 + kk) * 128 + c4 * 4]);
        }
        __syncthreads();

#pragma unroll 8
        for (int kk = 0; kk < 32; kk++) {
            float2 xp[4];
#pragma unroll
            for (int i = 0; i < 4; i++)
                xp[i] = *(const float2*)&xt[kk][base_r + 2 * i];
            float4 wa = *(const float4*)&ws[kk][c0];
            float4 wb = *(const float4*)&ws[kk][64 + c0];
            float2 wa0 = make_float2(wa.x, wa.y), wa1 = make_float2(wa.z, wa.w);
            float2 wb0 = make_float2(wb.x, wb.y), wb1 = make_float2(wb.z, wb.w);
#pragma unroll
            for (int i = 0; i < 4; i++) {
                float2 xd0 = make_float2(xp[i].x, xp[i].x);
                float2 xd1 = make_float2(xp[i].y, xp[i].y);
                ffma2(acc[2*i  ][0], xd0, wa0); ffma2(acc[2*i  ][1], xd0, wa1);
                ffma2(acc[2*i  ][2], xd0, wb0); ffma2(acc[2*i  ][3], xd0, wb1);
                ffma2(acc[2*i+1][0], xd1, wa0); ffma2(acc[2*i+1][1], xd1, wa1);
                ffma2(acc[2*i+1][2], xd1, wb0); ffma2(acc[2*i+1][3], xd1, wb1);
            }
        }
        __syncthreads();
    }

    float4 asA = __ldg((const float4*)&a_src[c0]);
    float4 adA = __ldg((const float4*)&a_dst[c0]);
    float4 asB = __ldg((const float4*)&a_src[64 + c0]);
    float4 adB = __ldg((const float4*)&a_dst[64 + c0]);
    int headA = cgrp >> 3;
    int headB = 2 + headA;

#pragma unroll
    for (int r = 0; r < 8; r++) {
        int row = row0 + base_r + r;
        float4 hA = make_float4(acc[r][0].x, acc[r][0].y, acc[r][1].x, acc[r][1].y);
        float4 hB = make_float4(acc[r][2].x, acc[r][2].y, acc[r][3].x, acc[r][3].y);
        if (row < N) {
            *(float4*)&g_h[(size_t)row * 128 + c0]      = hA;
            *(float4*)&g_h[(size_t)row * 128 + 64 + c0] = hB;
        }
        float paA = hA.x*asA.x + hA.y*asA.y + hA.z*asA.z + hA.w*asA.w;
        float pdA = hA.x*adA.x + hA.y*adA.y + hA.z*adA.z + hA.w*adA.w;
        float paB = hB.x*asB.x + hB.y*asB.y + hB.z*asB.z + hB.w*asB.w;
        float pdB = hB.x*adB.x + hB.y*adB.y + hB.z*adB.z + hB.w*adB.w;
#pragma unroll
        for (int o = 4; o >= 1; o >>= 1) {
            paA += __shfl_xor_sync(0xffffffffu, paA, o);
            pdA += __shfl_xor_sync(0xffffffffu, pdA, o);
            paB += __shfl_xor_sync(0xffffffffu, paB, o);
            pdB += __shfl_xor_sync(0xffffffffu, pdB, o);
        }
        if ((cgrp & 7) == 0 && row < N) {
            g_as[row * 4 + headA] = paA;
            g_ad[row * 4 + headA] = pdA;
            g_as[row * 4 + headB] = paB;
            g_ad[row * 4 + headB] = pdB;
        }
    }
}

// ---------------------------------------------------------------------------
// Aggregation: warp per dst node, online segment softmax, 4-edge chunks (MLP=4)
// g_off is shifted by fill: segment n = [n==0?0:g_off[n-1], g_off[n])
// ---------------------------------------------------------------------------
__global__ void agg_kernel(float* __restrict__ outparam, int out_to_gx2,
                           const float* __restrict__ bias, int relu, int N) {
    int lane = threadIdx.x & 31;
    int n = (blockIdx.x * blockDim.x + threadIdx.x) >> 5;
    if (n >= N) return;

    float* out = out_to_gx2 ? (float*)g_x2 : outparam;
    const float4* H4 = (const float4*)g_h;
    int head = lane >> 3;

    float adn = g_ad[n * 4 + head];
    float m = lrelu(g_as[n * 4 + head] + adn);
    float d = 1.f;
    float4 acc = H4[(size_t)n * 32 + lane];   // self loop, weight exp(0)=1

    int p  = (n == 0) ? 0 : __ldg(&g_off[n - 1]);
    int p1 = __ldg(&g_off[n]);

    for (; p + 4 <= p1; p += 4) {
        int s0 = __ldg(&g_csr[p]);
        int s1 = __ldg(&g_csr[p + 1]);
        int s2 = __ldg(&g_csr[p + 2]);
        int s3 = __ldg(&g_csr[p + 3]);
        float e0 = lrelu(g_as[s0 * 4 + head] + adn);
        float e1 = lrelu(g_as[s1 * 4 + head] + adn);
        float e2 = lrelu(g_as[s2 * 4 + head] + adn);
        float e3 = lrelu(g_as[s3 * 4 + head] + adn);
        float4 h0 = H4[(size_t)s0 * 32 + lane];
        float4 h1 = H4[(size_t)s1 * 32 + lane];
        float4 h2 = H4[(size_t)s2 * 32 + lane];
        float4 h3 = H4[(size_t)s3 * 32 + lane];
        float mc = fmaxf(fmaxf(e0, e1), fmaxf(e2, e3));
        if (mc > m) {
            float f = __expf(m - mc);
            acc.x *= f; acc.y *= f; acc.z *= f; acc.w *= f;
            d *= f;
            m = mc;
        }
        float w0 = __expf(e0 - m);
        float w1 = __expf(e1 - m);
        float w2 = __expf(e2 - m);
        float w3 = __expf(e3 - m);
        d += (w0 + w1) + (w2 + w3);
        acc.x += w0*h0.x + w1*h1.x + w2*h2.x + w3*h3.x;
        acc.y += w0*h0.y + w1*h1.y + w2*h2.y + w3*h3.y;
        acc.z += w0*h0.z + w1*h1.z + w2*h2.z + w3*h3.z;
        acc.w += w0*h0.w + w1*h1.w + w2*h2.w + w3*h3.w;
    }
    for (; p < p1; p++) {
        int s = __ldg(&g_csr[p]);
        float e = lrelu(g_as[s * 4 + head] + adn);
        float4 hv = H4[(size_t)s * 32 + lane];
        float wgt;
        if (e > m) {
            float f = __expf(m - e);
            acc.x *= f; acc.y *= f; acc.z *= f; acc.w *= f;
            d *= f;
            m = e;
            wgt = 1.f;
        } else {
            wgt = __expf(e - m);
        }
        d += wgt;
        acc.x += wgt * hv.x; acc.y += wgt * hv.y;
        acc.z += wgt * hv.z; acc.w += wgt * hv.w;
    }

    float inv = 1.f / (d + 1e-16f);
    float4 bb = __ldg((const float4*)bias + lane);
    float4 o;
    o.x = acc.x * inv + bb.x;
    o.y = acc.y * inv + bb.y;
    o.z = acc.z * inv + bb.z;
    o.w = acc.w * inv + bb.w;
    if (relu) {
        o.x = fmaxf(o.x, 0.f); o.y = fmaxf(o.y, 0.f);
        o.z = fmaxf(o.z, 0.f); o.w = fmaxf(o.w, 0.f);
    }
    ((float4*)out)[(size_t)n * 32 + lane] = o;
}

// ---------------------------------------------------------------------------
// Launch
// ---------------------------------------------------------------------------
extern "C" void kernel_launch(void* const* d_in, const int* in_sizes, int n_in,
                              void* d_out, int out_size) {
    const float* x   = (const float*)d_in[0];
    const int*   ei  = (const int*)d_in[1];
    const float* W1  = (const float*)d_in[2];
    const float* as1 = (const float*)d_in[3];
    const float* ad1 = (const float*)d_in[4];
    const float* b1  = (const float*)d_in[5];
    const float* W2  = (const float*)d_in[6];
    const float* as2 = (const float*)d_in[7];
    const float* ad2 = (const float*)d_in[8];
    const float* b2  = (const float*)d_in[9];

    int N = in_sizes[0] / 128;
    int E = in_sizes[1] / 2;

    // CSR build (reused by both layers)
    zero_kernel<<<(N + 255) / 256, 256>>>(N);
    hist_kernel<<<(E / 4 + 255) / 256, 256>>>(ei, E);
    scan_kernel<<<1, 1024>>>(N);
    fill_kernel<<<(E / 4 + 255) / 256, 256>>>(ei, E);

    int ggrid = (N + GR - 1) / GR;
    int agrid = (N + 7) / 8;

    // Layer 1
    gemm_ffma2_kernel<<<ggrid, 128>>>(x, 0, W1, as1, ad1, N);
    agg_kernel<<<agrid, 256>>>(nullptr, 1, b1, 1, N);

    // Layer 2
    gemm_ffma2_kernel<<<ggrid, 128>>>(nullptr, 1, W2, as2, ad2, N);
    agg_kernel<<<agrid, 256>>>((float*)d_out, 0, b2, 0, N);
}